// round 4
// baseline (speedup 1.0000x reference)
#include <cuda_runtime.h>

#define BN   4
#define LL   512
#define HH   768
#define HSZ  64
#define NOUT 16
#define NTOK (BN*LL)      // 2048
#define NP   131328       // L*(L+1)/2
#define NKQ  16           // split-K factor
#define KQ   (HH/NKQ)     // 48

typedef unsigned long long u64;

// packed fp32x2 helpers (SASS FFMA2 — ptxas never emits this from C++)
__device__ __forceinline__ u64 pk2(float v) {
    u64 r; asm("mov.b64 %0, {%1, %1};" : "=l"(r) : "f"(v)); return r;
}
__device__ __forceinline__ void fma2(u64& d, u64 a, u64 b) {
    asm("fma.rn.f32x2 %0, %1, %2, %0;" : "+l"(d) : "l"(a), "l"(b));
}
__device__ __forceinline__ void upk2(float& lo, float& hi, u64 v) {
    asm("mov.b64 {%0, %1}, %2;" : "=f"(lo), "=f"(hi) : "l"(v));
}

// scratch (allocation-free rule: __device__ globals)
__device__ float g_part[NKQ*NTOK*128]; // 16 MB split-K partials [kq][tok][n]
__device__ float g_q[NTOK*HSZ];        // 512 KB
__device__ float g_k[NTOK*HSZ];        // 512 KB
__device__ float g_A[NTOK*NOUT];       // 128 KB
__device__ float g_E[NTOK*NOUT];       // 128 KB
__device__ float g_S[BN*LL*LL];        // 4 MB

// ---------------------------------------------------------------------------
// Kernel 1: split-K partial GEMM with packed f32x2 FMA.
// 16 token-tiles (128 tok) x 16 K-slices (48) = 256 blocks, 2 blocks/SM.
// Per-thread 8x8 tile held as 8x4 f32x2 accumulators (paired along N so the
// ws operand loads directly as ulonglong2; broadcast am is duplicated via
// mov.b64 on the alu pipe).
// ---------------------------------------------------------------------------
__global__ __launch_bounds__(256, 2) void proj_partial_kernel(
    const float* __restrict__ x,
    const float* __restrict__ Wq,
    const float* __restrict__ Wk)
{
    __shared__ float xs[16][132];    // [k][token]
    __shared__ float ws[16][128];    // [k][n] n<64 -> Wq col else Wk col

    const int tid = threadIdx.x;
    const int tt  = blockIdx.x & 15;
    const int kq  = blockIdx.x >> 4;
    const int t0  = tt * 128;
    const int k0  = kq * KQ;
    const int n0  = (tid & 15) * 8;
    const int m0  = (tid >> 4) * 8;

    u64 acc2[8][4];
    #pragma unroll
    for (int i = 0; i < 8; i++)
        #pragma unroll
        for (int j = 0; j < 4; j++) acc2[i][j] = 0ull;

    for (int kk = k0; kk < k0 + KQ; kk += 16) {
        #pragma unroll
        for (int p = 0; p < 8; p++) {
            int e = tid + p * 256;
            int tok = e >> 4, d = e & 15;
            xs[d][tok] = x[(t0 + tok) * HH + kk + d];
        }
        #pragma unroll
        for (int p = 0; p < 8; p++) {
            int e = tid + p * 256;
            int n = e & 127, d = e >> 7;
            ws[d][n] = (n < 64) ? Wq[(kk + d) * HSZ + n]
                                : Wk[(kk + d) * HSZ + (n - 64)];
        }
        __syncthreads();
        #pragma unroll
        for (int kd = 0; kd < 16; kd++) {
            float4 a0 = *(const float4*)&xs[kd][m0];
            float4 a1 = *(const float4*)&xs[kd][m0 + 4];
            ulonglong2 w0 = *(const ulonglong2*)&ws[kd][n0];
            ulonglong2 w1 = *(const ulonglong2*)&ws[kd][n0 + 4];
            u64 am2[8] = {pk2(a0.x), pk2(a0.y), pk2(a0.z), pk2(a0.w),
                          pk2(a1.x), pk2(a1.y), pk2(a1.z), pk2(a1.w)};
            u64 wn2[4] = {w0.x, w0.y, w1.x, w1.y};
            #pragma unroll
            for (int i = 0; i < 8; i++)
                #pragma unroll
                for (int j = 0; j < 4; j++) fma2(acc2[i][j], am2[i], wn2[j]);
        }
        __syncthreads();
    }

    #pragma unroll
    for (int i = 0; i < 8; i++) {
        float r[8];
        #pragma unroll
        for (int j = 0; j < 4; j++) upk2(r[2*j], r[2*j+1], acc2[i][j]);
        float* gp = g_part + ((size_t)kq * NTOK + t0 + m0 + i) * 128 + n0;
        *(float4*)&gp[0] = make_float4(r[0], r[1], r[2], r[3]);
        *(float4*)&gp[4] = make_float4(r[4], r[5], r[6], r[7]);
    }
}

// ---------------------------------------------------------------------------
// Kernel 2: reduce split-K partials + bias -> g_q/g_k, then A/E tables with
// Wb staged in shared. 64 blocks x 32 tokens.
// A[s,o] = q[s]@Wb[0:64] + bb
// E[e,o] = k[e]@(Wb[64:128]+Wb[192:256]) + q[e]@Wb[128:192]
// ---------------------------------------------------------------------------
__global__ __launch_bounds__(256) void reduce_ae_kernel(
    const float* __restrict__ bq, const float* __restrict__ bk,
    const float* __restrict__ bb, const float* __restrict__ Wb)
{
    __shared__ float Wbs[256 * NOUT];
    __shared__ float sQK[32][132];
    __shared__ float bbs[NOUT];
    __shared__ float bqs[HSZ], bks[HSZ];

    const int tid = threadIdx.x;
    const int t0  = blockIdx.x * 32;

    #pragma unroll
    for (int p = 0; p < 16; p++)
        Wbs[tid + p * 256] = Wb[tid + p * 256];
    if (tid < NOUT) bbs[tid] = bb[tid];
    if (tid < HSZ)  { bqs[tid] = bq[tid]; bks[tid] = bk[tid]; }
    __syncthreads();

    const float4* gp4 = (const float4*)g_part;
    #pragma unroll
    for (int p = 0; p < 4; p++) {
        int e  = tid + p * 256;
        int tok = e >> 5, n4 = e & 31;
        size_t gi = (size_t)(t0 + tok) * 32 + n4;
        float4 v = make_float4(0.f, 0.f, 0.f, 0.f);
        #pragma unroll
        for (int q = 0; q < NKQ; q++) {
            float4 pv = gp4[(size_t)q * NTOK * 32 + gi];
            v.x += pv.x; v.y += pv.y; v.z += pv.z; v.w += pv.w;
        }
        int n = n4 * 4;
        if (n < 64) { v.x += bqs[n]; v.y += bqs[n+1]; v.z += bqs[n+2]; v.w += bqs[n+3]; }
        else        { v.x += bks[n-64]; v.y += bks[n-63]; v.z += bks[n-62]; v.w += bks[n-61]; }
        *(float4*)&sQK[tok][n] = v;
        int tok_g = t0 + tok;
        if (n4 < 16) ((float4*)(g_q + tok_g * HSZ))[n4]      = v;
        else         ((float4*)(g_k + tok_g * HSZ))[n4 - 16] = v;
    }
    __syncthreads();

    #pragma unroll
    for (int p = 0; p < 4; p++) {
        int e2   = tid + p * 256;
        int tokL = e2 >> 5;            // warp-uniform -> sQK broadcast reads
        int oo   = e2 & 31;
        int tok  = t0 + tokL;
        if (oo < NOUT) {
            int o = oo;
            float a = bbs[o];
            #pragma unroll 8
            for (int h = 0; h < 64; h++)
                a += sQK[tokL][h] * Wbs[h * NOUT + o];
            g_A[tok * NOUT + o] = a;
        } else {
            int o = oo - NOUT;
            float a = 0.f;
            #pragma unroll 8
            for (int h = 0; h < 64; h++) {
                a += sQK[tokL][64 + h] * (Wbs[(64 + h) * NOUT + o] + Wbs[(192 + h) * NOUT + o]);
                a += sQK[tokL][h]      *  Wbs[(128 + h) * NOUT + o];
            }
            g_E[tok * NOUT + o] = a;
        }
    }
}

// ---------------------------------------------------------------------------
// Kernel 3: S[b] = Q[b] @ K[b]^T with f32x2 FMA. 64x64 tiles; below-diagonal
// tiles early-exit.
// ---------------------------------------------------------------------------
__global__ __launch_bounds__(256) void score_kernel()
{
    const int bx = blockIdx.x;   // e tile
    const int by = blockIdx.y;   // s tile
    if (by > bx) return;
    const int b  = blockIdx.z;

    __shared__ float qs[64][68];
    __shared__ float ks[64][68];

    const int tid = threadIdx.x;
    const float* qb = g_q + (b * LL + by * 64) * HSZ;
    const float* kb = g_k + (b * LL + bx * 64) * HSZ;

    #pragma unroll
    for (int p = 0; p < 16; p++) {
        int e = tid + p * 256;
        int r = e >> 6, h = e & 63;
        qs[h][r] = qb[r * HSZ + h];
        ks[h][r] = kb[r * HSZ + h];
    }
    __syncthreads();

    const int m0 = (tid >> 4) * 4;
    const int n0 = (tid & 15) * 4;
    u64 acc2[4][2];
    #pragma unroll
    for (int i = 0; i < 4; i++) { acc2[i][0] = 0ull; acc2[i][1] = 0ull; }

    #pragma unroll
    for (int h = 0; h < 64; h++) {
        float4 a = *(const float4*)&qs[h][m0];
        ulonglong2 vv = *(const ulonglong2*)&ks[h][n0];
        u64 am2[4] = {pk2(a.x), pk2(a.y), pk2(a.z), pk2(a.w)};
        #pragma unroll
        for (int i = 0; i < 4; i++) {
            fma2(acc2[i][0], am2[i], vv.x);
            fma2(acc2[i][1], am2[i], vv.y);
        }
    }

    float* Sp = g_S + (size_t)b * LL * LL + (by * 64 + m0) * LL + bx * 64 + n0;
    #pragma unroll
    for (int i = 0; i < 4; i++) {
        float r[4];
        upk2(r[0], r[1], acc2[i][0]);
        upk2(r[2], r[3], acc2[i][1]);
        *(float4*)&Sp[i * LL] = make_float4(r[0], r[1], r[2], r[3]);
    }
}

// ---------------------------------------------------------------------------
// Kernel 4: scatter. One block per (b, s); one thread owns one pair-row
// (16 floats = 4 float4 loads of E + 4 float4 stores).
// out[b, off(s)+j, :] = S[b,s,s+j] + A[b,s,:] + E[b,s+j,:]
// ---------------------------------------------------------------------------
__global__ __launch_bounds__(256) void scatter_kernel(float* __restrict__ out)
{
    const int s = blockIdx.x;
    const int b = blockIdx.y;

    __shared__ float  Ss[LL];
    __shared__ float4 Ash[4];

    const int nE = LL - s;
    const float* Srow = g_S + (size_t)b * LL * LL + (size_t)s * LL + s;
    for (int i = threadIdx.x; i < nE; i += 256) Ss[i] = Srow[i];
    if (threadIdx.x < 4)
        Ash[threadIdx.x] = ((const float4*)(g_A + (b * LL + s) * NOUT))[threadIdx.x];
    __syncthreads();

    const float4 a0 = Ash[0], a1 = Ash[1], a2 = Ash[2], a3 = Ash[3];
    const int base = b * NP + s * LL - (s * (s - 1)) / 2;
    const float4* E4   = (const float4*)(g_E + b * LL * NOUT) + (size_t)s * 4;
    float4*       out4 = (float4*)(out + (size_t)base * NOUT);

    for (int j = threadIdx.x; j < nE; j += 256) {
        float sv = Ss[j];
        float4 e0 = E4[j * 4 + 0];
        float4 e1 = E4[j * 4 + 1];
        float4 e2 = E4[j * 4 + 2];
        float4 e3 = E4[j * 4 + 3];
        out4[j * 4 + 0] = make_float4(sv + a0.x + e0.x, sv + a0.y + e0.y,
                                      sv + a0.z + e0.z, sv + a0.w + e0.w);
        out4[j * 4 + 1] = make_float4(sv + a1.x + e1.x, sv + a1.y + e1.y,
                                      sv + a1.z + e1.z, sv + a1.w + e1.w);
        out4[j * 4 + 2] = make_float4(sv + a2.x + e2.x, sv + a2.y + e2.y,
                                      sv + a2.z + e2.z, sv + a2.w + e2.w);
        out4[j * 4 + 3] = make_float4(sv + a3.x + e3.x, sv + a3.y + e3.y,
                                      sv + a3.z + e3.z, sv + a3.w + e3.w);
    }
}

extern "C" void kernel_launch(void* const* d_in, const int* in_sizes, int n_in,
                              void* d_out, int out_size)
{
    const float* x  = (const float*)d_in[0];
    const float* Wq = (const float*)d_in[1];
    const float* bq = (const float*)d_in[2];
    const float* Wk = (const float*)d_in[3];
    const float* bk = (const float*)d_in[4];
    const float* Wb = (const float*)d_in[5];
    const float* bb = (const float*)d_in[6];
    float* out = (float*)d_out;

    proj_partial_kernel<<<256, 256>>>(x, Wq, Wk);
    reduce_ae_kernel<<<64, 256>>>(bq, bk, bb, Wb);
    dim3 g2(LL / 64, LL / 64, BN);
    score_kernel<<<g2, 256>>>();
    dim3 g3(LL, BN);
    scatter_kernel<<<g3, 256>>>(out);
}